// round 5
// baseline (speedup 1.0000x reference)
#include <cuda_runtime.h>
#include <cstdint>
#include <float.h>

// Problem constants
#define BB 4
#define LL 4096
#define DHQ 1024
#define TTQ 1024
#define DGQ 768
#define PPQ 256

// Scratch (__device__ globals; no cudaMalloc allowed)
__device__ float g_K[(size_t)BB * LL * PPQ];   // 16 MB
__device__ float g_Q[(size_t)BB * TTQ * PPQ];  //  4 MB
__device__ float g_S[(size_t)BB * TTQ * LL];   // 64 MB

// ---------------------------------------------------------------------------
// helpers
// ---------------------------------------------------------------------------
__device__ __forceinline__ uint32_t f2tf32(float x) {
    uint32_t r;
    asm("cvt.rna.tf32.f32 %0, %1;" : "=r"(r) : "f"(x));
    return r;
}

__device__ __forceinline__ void mma_tf32(float* d, const uint32_t* a, const uint32_t* b) {
    asm volatile(
        "mma.sync.aligned.m16n8k8.row.col.f32.tf32.tf32.f32 "
        "{%0,%1,%2,%3}, {%4,%5,%6,%7}, {%8,%9}, {%0,%1,%2,%3};"
        : "+f"(d[0]), "+f"(d[1]), "+f"(d[2]), "+f"(d[3])
        : "r"(a[0]), "r"(a[1]), "r"(a[2]), "r"(a[3]), "r"(b[0]), "r"(b[1]));
}

__device__ __forceinline__ void cp16(float* sdst, const float* gsrc) {
    uint32_t a = (uint32_t)__cvta_generic_to_shared(sdst);
    asm volatile("cp.async.cg.shared.global [%0], [%1], 16;" :: "r"(a), "l"(gsrc));
}
#define CP_COMMIT() asm volatile("cp.async.commit_group;" ::: "memory")
#define CP_WAIT1()  asm volatile("cp.async.wait_group 1;" ::: "memory")

// ---------------------------------------------------------------------------
// tf32 tensor-core GEMM, 3xTF32 split with split-on-load:
//   C[M,N] = scale * A[M,K] * op(B);  BT: B is [N,K] (NT) else [K,N] (NN)
// Block tile 128x128, BK=32, 256 threads (8 warps, 64x32 warp tiles).
// SMEM: 3 stages of raw f32 {A[128][36], B[128][36] or [32][136(+pad)]}.
// Optional per-column int32 mask (logits): nonzero -> -FLT_MAX.
// ---------------------------------------------------------------------------
#define ASLOT 4608                    // floats (128*36)
#define STAGE_FL 9216                 // A slot + B slot
#define NSTAGE 3
#define SMEM_GEMM (NSTAGE * STAGE_FL * 4)   // 110592 bytes

template <bool BT>
__global__ __launch_bounds__(256)
void tf32_mma_gemm(const float* __restrict__ A, const float* __restrict__ B,
                   float* __restrict__ C,
                   int K, long lda, long ldb, long ldc,
                   long sA, long sB, long sC,
                   float scale, const int* __restrict__ mask, long maskStride)
{
    extern __shared__ float sm[];

    const int tid  = threadIdx.x;
    const int wid  = tid >> 5;
    const int lane = tid & 31;
    const int grp  = lane >> 2;       // 0..7
    const int tig  = lane & 3;        // 0..3
    const int wm   = (wid & 1) * 64;  // warp m offset
    const int wn   = (wid >> 1) * 32; // warp n offset

    const int bz = blockIdx.z;
    A += (long)bz * sA;
    B += (long)bz * sB;
    C += (long)bz * sC;
    if (mask) mask += (long)bz * maskStride;

    const long row0 = (long)blockIdx.y * 128;
    const long col0 = (long)blockIdx.x * 128;

    const int nIter = K >> 5;   // BK = 32

    auto issue_stage = [&](int it) {
        float* sa = sm + (it % NSTAGE) * STAGE_FL;
        float* sb = sa + ASLOT;
        const float* pA = A + row0 * lda + (long)it * 32;
#pragma unroll
        for (int p = 0; p < 4; ++p) {
            const int f = p * 256 + tid;
            const int m = f >> 3, kc = (f & 7) * 4;
            cp16(sa + m * 36 + kc, pA + (long)m * lda + kc);
        }
        if (BT) {
            const float* pB = B + col0 * ldb + (long)it * 32;
#pragma unroll
            for (int p = 0; p < 4; ++p) {
                const int f = p * 256 + tid;
                const int n = f >> 3, kc = (f & 7) * 4;
                cp16(sb + n * 36 + kc, pB + (long)n * ldb + kc);
            }
        } else {
            const float* pB = B + (long)it * 32 * ldb + col0;
#pragma unroll
            for (int p = 0; p < 4; ++p) {
                const int f = p * 256 + tid;
                const int k = f >> 5, nc = (f & 31) * 4;
                cp16(sb + k * 136 + nc, pB + (long)k * ldb + nc);
            }
        }
    };

    float acc[4][4][4];
#pragma unroll
    for (int i = 0; i < 4; ++i)
#pragma unroll
        for (int j = 0; j < 4; ++j)
#pragma unroll
            for (int r = 0; r < 4; ++r) acc[i][j][r] = 0.0f;

    // Prefetch first NSTAGE-1 stages
    issue_stage(0); CP_COMMIT();
    if (nIter > 1) issue_stage(1);
    CP_COMMIT();

    for (int it = 0; it < nIter; ++it) {
        CP_WAIT1();            // stage `it` resident
        __syncthreads();       // visible to all warps; prior stage fully consumed

        if (it + 2 < nIter) issue_stage(it + 2);
        CP_COMMIT();           // always commit (possibly empty) to keep counts

        const float* sa = sm + (it % NSTAGE) * STAGE_FL;
        const float* sb = sa + ASLOT;

#pragma unroll
        for (int ks = 0; ks < 4; ++ks) {
            const int c = ks * 8 + tig;
            uint32_t fAH[4][4], fAL[4][4], fBH[4][2], fBL[4][2];
#pragma unroll
            for (int i = 0; i < 4; ++i) {
                const int r = wm + i * 16 + grp;
                float v0 = sa[r * 36 + c];
                float v1 = sa[(r + 8) * 36 + c];
                float v2 = sa[r * 36 + c + 4];
                float v3 = sa[(r + 8) * 36 + c + 4];
                fAH[i][0] = f2tf32(v0); fAL[i][0] = f2tf32(v0 - __uint_as_float(fAH[i][0]));
                fAH[i][1] = f2tf32(v1); fAL[i][1] = f2tf32(v1 - __uint_as_float(fAH[i][1]));
                fAH[i][2] = f2tf32(v2); fAL[i][2] = f2tf32(v2 - __uint_as_float(fAH[i][2]));
                fAH[i][3] = f2tf32(v3); fAL[i][3] = f2tf32(v3 - __uint_as_float(fAH[i][3]));
            }
#pragma unroll
            for (int j = 0; j < 4; ++j) {
                const int n = wn + j * 8 + grp;
                float v0, v1;
                if (BT) {
                    v0 = sb[n * 36 + c];
                    v1 = sb[n * 36 + c + 4];
                } else {
                    v0 = sb[c * 136 + n];
                    v1 = sb[(c + 4) * 136 + n];
                }
                fBH[j][0] = f2tf32(v0); fBL[j][0] = f2tf32(v0 - __uint_as_float(fBH[j][0]));
                fBH[j][1] = f2tf32(v1); fBL[j][1] = f2tf32(v1 - __uint_as_float(fBH[j][1]));
            }
#pragma unroll
            for (int i = 0; i < 4; ++i)
#pragma unroll
                for (int j = 0; j < 4; ++j) {
                    mma_tf32(acc[i][j], fAH[i], fBH[j]);
                    mma_tf32(acc[i][j], fAH[i], fBL[j]);
                    mma_tf32(acc[i][j], fAL[i], fBH[j]);
                }
        }
        __syncthreads();       // all warps done with stage `it` before rewrite
    }

    // Epilogue: register -> gmem (float2 per row-pair), scale + mask
#pragma unroll
    for (int i = 0; i < 4; ++i) {
        const long r0 = row0 + wm + i * 16 + grp;
#pragma unroll
        for (int j = 0; j < 4; ++j) {
            const long gc = col0 + wn + j * 8 + tig * 2;
            float x0 = acc[i][j][0] * scale, x1 = acc[i][j][1] * scale;
            float y0 = acc[i][j][2] * scale, y1 = acc[i][j][3] * scale;
            if (mask) {
                const bool m0 = mask[gc] != 0, m1 = mask[gc + 1] != 0;
                if (m0) { x0 = -FLT_MAX; y0 = -FLT_MAX; }
                if (m1) { x1 = -FLT_MAX; y1 = -FLT_MAX; }
            }
            *reinterpret_cast<float2*>(C + r0 * ldc + gc)       = make_float2(x0, x1);
            *reinterpret_cast<float2*>(C + (r0 + 8) * ldc + gc) = make_float2(y0, y1);
        }
    }
}

// ---------------------------------------------------------------------------
// Row softmax over LL (float4 I/O)
// ---------------------------------------------------------------------------
__global__ __launch_bounds__(256)
void softmax_kernel(float* __restrict__ S)
{
    __shared__ float4 buf[LL / 4];
    __shared__ float red[256];

    const int tid = threadIdx.x;
    float4* p = reinterpret_cast<float4*>(S + (long)blockIdx.x * LL);

    float m = -FLT_MAX;
#pragma unroll
    for (int i = tid; i < LL / 4; i += 256) {
        float4 v = p[i];
        buf[i] = v;
        m = fmaxf(m, fmaxf(fmaxf(v.x, v.y), fmaxf(v.z, v.w)));
    }
    red[tid] = m;
    __syncthreads();
    for (int s = 128; s > 0; s >>= 1) {
        if (tid < s) red[tid] = fmaxf(red[tid], red[tid + s]);
        __syncthreads();
    }
    m = red[0];
    __syncthreads();

    float sum = 0.0f;
#pragma unroll
    for (int i = tid; i < LL / 4; i += 256) {
        float4 v = buf[i];
        v.x = __expf(v.x - m); v.y = __expf(v.y - m);
        v.z = __expf(v.z - m); v.w = __expf(v.w - m);
        buf[i] = v;
        sum += v.x + v.y + v.z + v.w;
    }
    red[tid] = sum;
    __syncthreads();
    for (int s = 128; s > 0; s >>= 1) {
        if (tid < s) red[tid] += red[tid + s];
        __syncthreads();
    }
    const float inv = 1.0f / red[0];

#pragma unroll
    for (int i = tid; i < LL / 4; i += 256) {
        float4 v = buf[i];
        v.x *= inv; v.y *= inv; v.z *= inv; v.w *= inv;
        p[i] = v;
    }
}

// ---------------------------------------------------------------------------
// Launch. Inputs: H [B,L,DH] f32, G [B,T,DG] f32, mask [B,L] int32,
// Wk_w [P,DH] f32, Wq_w [P,DG] f32. Output Z [B,T,DH] f32.
// ---------------------------------------------------------------------------
extern "C" void kernel_launch(void* const* d_in, const int* in_sizes, int n_in,
                              void* d_out, int out_size)
{
    const float* H    = (const float*)d_in[0];
    const float* G    = (const float*)d_in[1];
    const int*   mask = (const int*)d_in[2];
    const float* Wk   = (const float*)d_in[3];
    const float* Wq   = (const float*)d_in[4];
    float*       Z    = (float*)d_out;

    float *gK, *gQ, *gS;
    cudaGetSymbolAddress((void**)&gK, g_K);
    cudaGetSymbolAddress((void**)&gQ, g_Q);
    cudaGetSymbolAddress((void**)&gS, g_S);

    cudaFuncSetAttribute(tf32_mma_gemm<true>,
                         cudaFuncAttributeMaxDynamicSharedMemorySize, SMEM_GEMM);
    cudaFuncSetAttribute(tf32_mma_gemm<false>,
                         cudaFuncAttributeMaxDynamicSharedMemorySize, SMEM_GEMM);

    // 1) K = H * Wk^T : [B*L, DH] x [P, DH]^T -> [B*L, P]
    tf32_mma_gemm<true><<<dim3(PPQ / 128, (BB * LL) / 128, 1), 256, SMEM_GEMM>>>(
        H, Wk, gK, DHQ, DHQ, DHQ, PPQ, 0, 0, 0, 1.0f, nullptr, 0);

    // 2) Q = G * Wq^T : [B*T, DG] x [P, DG]^T -> [B*T, P]
    tf32_mma_gemm<true><<<dim3(PPQ / 128, (BB * TTQ) / 128, 1), 256, SMEM_GEMM>>>(
        G, Wq, gQ, DGQ, DGQ, DGQ, PPQ, 0, 0, 0, 1.0f, nullptr, 0);

    // 3) S = scale * Q * K^T (masked) : per batch [T, P] x [L, P]^T -> [T, L]
    tf32_mma_gemm<true><<<dim3(LL / 128, TTQ / 128, BB), 256, SMEM_GEMM>>>(
        gQ, gK, gS, PPQ, PPQ, PPQ, LL,
        (long)TTQ * PPQ, (long)LL * PPQ, (long)TTQ * LL,
        0.0625f, mask, (long)LL);

    // 4) softmax over L
    softmax_kernel<<<BB * TTQ, 256>>>(gS);

    // 5) Z = alpha * H : per batch [T, L] x [L, DH] (NN) -> [T, DH]
    tf32_mma_gemm<false><<<dim3(DHQ / 128, TTQ / 128, BB), 256, SMEM_GEMM>>>(
        gS, H, Z, LL, LL, DHQ, DHQ,
        (long)TTQ * LL, (long)LL * DHQ, (long)TTQ * DHQ,
        1.0f, nullptr, 0);
}

// round 6
// speedup vs baseline: 1.6267x; 1.6267x over previous
#include <cuda_runtime.h>
#include <cuda_fp16.h>
#include <cstdint>
#include <float.h>

// Problem constants
#define BB 4
#define LL 4096
#define DHQ 1024
#define TTQ 1024
#define DGQ 768
#define PPQ 256

// Scratch (__device__ globals; no cudaMalloc allowed)
__device__ float g_K[(size_t)BB * LL * PPQ];   // 16 MB
__device__ float g_Q[(size_t)BB * TTQ * PPQ];  //  4 MB
__device__ float g_S[(size_t)BB * TTQ * LL];   // 64 MB

// ---------------------------------------------------------------------------
// helpers
// ---------------------------------------------------------------------------
__device__ __forceinline__ void mma_fp16(float* d, const uint32_t* a, const uint32_t* b) {
    asm volatile(
        "mma.sync.aligned.m16n8k16.row.col.f32.f16.f16.f32 "
        "{%0,%1,%2,%3}, {%4,%5,%6,%7}, {%8,%9}, {%0,%1,%2,%3};"
        : "+f"(d[0]), "+f"(d[1]), "+f"(d[2]), "+f"(d[3])
        : "r"(a[0]), "r"(a[1]), "r"(a[2]), "r"(a[3]), "r"(b[0]), "r"(b[1]));
}

__device__ __forceinline__ uint32_t h2_u32(__half2 h) {
    return *reinterpret_cast<uint32_t*>(&h);
}

// Split float pair -> (hi half2, lo half2). fp16 products are exact in fp32,
// so hi*hi + hi*lo + lo*hi captures all but ~2^-22 of the product.
__device__ __forceinline__ void split2(float x, float y, uint32_t& hi, uint32_t& lo) {
    __half2 h = __floats2half2_rn(x, y);
    float2 hb = __half22float2(h);
    __half2 l = __floats2half2_rn(x - hb.x, y - hb.y);
    hi = h2_u32(h);
    lo = h2_u32(l);
}

// ---------------------------------------------------------------------------
// fp16x3 tensor-core GEMM: C[M,N] = scale * A[M,K] * op(B)
//   BT=true : B is [N,K] row-major (NT)
//   BT=false: B is [K,N] row-major (NN)
// Block tile 128x128, BK=32, 256 threads (8 warps, 64x32 warp tiles).
// SMEM stages hold PRE-SPLIT half data:
//   A_hi [128][40] halves @0, A_lo @5120
//   NT B: B_hi [128][40] @10240, B_lo @15360   (both [row][k], k-pairs packed)
//   NN B: B_hi [32][136] @10240, B_lo @14592   ([k][n] halves)
// Stage = 20480 halves = 40960 B; 2 stages.
// Optional per-column int32 mask (logits): nonzero -> -FLT_MAX.
// ---------------------------------------------------------------------------
#define STAGE_H 20480
#define SMEM_GEMM (2 * STAGE_H * 2)   // 81920 bytes

template <bool BT>
__global__ __launch_bounds__(256)
void fp16x3_gemm(const float* __restrict__ A, const float* __restrict__ B,
                 float* __restrict__ C,
                 int K, long lda, long ldb, long ldc,
                 long sA, long sB, long sC,
                 float scale, const int* __restrict__ mask, long maskStride)
{
    extern __shared__ __align__(16) uint16_t smh[];

    const int tid  = threadIdx.x;
    const int wid  = tid >> 5;
    const int lane = tid & 31;
    const int grp  = lane >> 2;       // 0..7
    const int tig  = lane & 3;        // 0..3
    const int wm   = (wid & 1) * 64;  // warp m offset
    const int wn   = (wid >> 1) * 32; // warp n offset

    const int bz = blockIdx.z;
    A += (long)bz * sA;
    B += (long)bz * sB;
    C += (long)bz * sC;
    if (mask) mask += (long)bz * maskStride;

    const long row0 = (long)blockIdx.y * 128;
    const long col0 = (long)blockIdx.x * 128;

    const int nIter = K >> 5;   // BK = 32

    float4 rA[4], rB[4];

    auto load_tile = [&](int it) {
        const float* pA = A + row0 * lda + (long)it * 32;
#pragma unroll
        for (int p = 0; p < 4; ++p) {
            const int f = p * 256 + tid;
            rA[p] = *reinterpret_cast<const float4*>(pA + (long)(f >> 3) * lda + (f & 7) * 4);
        }
        if (BT) {
            const float* pB = B + col0 * ldb + (long)it * 32;
#pragma unroll
            for (int p = 0; p < 4; ++p) {
                const int f = p * 256 + tid;
                rB[p] = *reinterpret_cast<const float4*>(pB + (long)(f >> 3) * ldb + (f & 7) * 4);
            }
        } else {
            const float* pB = B + (long)it * 32 * ldb + col0;
#pragma unroll
            for (int p = 0; p < 4; ++p) {
                const int f = p * 256 + tid;
                rB[p] = *reinterpret_cast<const float4*>(pB + (long)(f >> 5) * ldb + (f & 31) * 4);
            }
        }
    };

    auto store_tile = [&](uint16_t* st) {
#pragma unroll
        for (int p = 0; p < 4; ++p) {
            const int f = p * 256 + tid;
            {   // A: [m][40] halves, hi @0, lo @5120
                const int m = f >> 3, kc = (f & 7) * 4;
                float4 v = rA[p];
                uint32_t h0, l0, h1, l1;
                split2(v.x, v.y, h0, l0);
                split2(v.z, v.w, h1, l1);
                *reinterpret_cast<uint2*>(st + m * 40 + kc)        = make_uint2(h0, h1);
                *reinterpret_cast<uint2*>(st + 5120 + m * 40 + kc) = make_uint2(l0, l1);
            }
            if (BT) {   // B: [n][40] halves, hi @10240, lo @15360
                const int n = f >> 3, kc = (f & 7) * 4;
                float4 v = rB[p];
                uint32_t h0, l0, h1, l1;
                split2(v.x, v.y, h0, l0);
                split2(v.z, v.w, h1, l1);
                *reinterpret_cast<uint2*>(st + 10240 + n * 40 + kc) = make_uint2(h0, h1);
                *reinterpret_cast<uint2*>(st + 15360 + n * 40 + kc) = make_uint2(l0, l1);
            } else {    // B: [k][136] halves, hi @10240, lo @14592
                const int k = f >> 5, nc = (f & 31) * 4;
                float4 v = rB[p];
                uint32_t h0, l0, h1, l1;
                split2(v.x, v.y, h0, l0);
                split2(v.z, v.w, h1, l1);
                *reinterpret_cast<uint2*>(st + 10240 + k * 136 + nc) = make_uint2(h0, h1);
                *reinterpret_cast<uint2*>(st + 14592 + k * 136 + nc) = make_uint2(l0, l1);
            }
        }
    };

    float acc[4][4][4];
#pragma unroll
    for (int i = 0; i < 4; ++i)
#pragma unroll
        for (int j = 0; j < 4; ++j)
#pragma unroll
            for (int r = 0; r < 4; ++r) acc[i][j][r] = 0.0f;

    load_tile(0);
    store_tile(smh);
    __syncthreads();

    for (int it = 0; it < nIter; ++it) {
        const bool more = (it + 1 < nIter);
        if (more) load_tile(it + 1);

        const uint16_t* st = smh + (it & 1) * STAGE_H;
        const uint32_t* sw = reinterpret_cast<const uint32_t*>(st);

#pragma unroll
        for (int ks = 0; ks < 2; ++ks) {
            uint32_t aH[4][4], aL[4][4], bH[4][2], bL[4][2];
#pragma unroll
            for (int i = 0; i < 4; ++i) {
                const int r  = wm + i * 16 + grp;
                const int w0 = r * 20 + tig + 8 * ks;
                const int w1 = (r + 8) * 20 + tig + 8 * ks;
                aH[i][0] = sw[w0];        aH[i][1] = sw[w1];
                aH[i][2] = sw[w0 + 4];    aH[i][3] = sw[w1 + 4];
                aL[i][0] = sw[2560 + w0]; aL[i][1] = sw[2560 + w1];
                aL[i][2] = sw[2560 + w0 + 4]; aL[i][3] = sw[2560 + w1 + 4];
            }
#pragma unroll
            for (int j = 0; j < 4; ++j) {
                const int n = wn + j * 8 + grp;
                if (BT) {
                    const int w0 = 5120 + n * 20 + tig + 8 * ks;
                    bH[j][0] = sw[w0];        bH[j][1] = sw[w0 + 4];
                    bL[j][0] = sw[2560 + w0]; bL[j][1] = sw[2560 + w0 + 4];
                } else {
                    const int kb = 2 * tig + 16 * ks;
                    const uint16_t* bh = st + 10240;
                    const uint16_t* bl = st + 14592;
                    bH[j][0] = (uint32_t)bh[kb * 136 + n]       | ((uint32_t)bh[(kb + 1) * 136 + n] << 16);
                    bH[j][1] = (uint32_t)bh[(kb + 8) * 136 + n] | ((uint32_t)bh[(kb + 9) * 136 + n] << 16);
                    bL[j][0] = (uint32_t)bl[kb * 136 + n]       | ((uint32_t)bl[(kb + 1) * 136 + n] << 16);
                    bL[j][1] = (uint32_t)bl[(kb + 8) * 136 + n] | ((uint32_t)bl[(kb + 9) * 136 + n] << 16);
                }
            }
#pragma unroll
            for (int i = 0; i < 4; ++i)
#pragma unroll
                for (int j = 0; j < 4; ++j) {
                    mma_fp16(acc[i][j], aH[i], bH[j]);
                    mma_fp16(acc[i][j], aH[i], bL[j]);
                    mma_fp16(acc[i][j], aL[i], bH[j]);
                }
        }

        if (more) store_tile(smh + ((it + 1) & 1) * STAGE_H);
        __syncthreads();
    }

    // Epilogue: register -> gmem (float2 per row-pair), scale + mask
#pragma unroll
    for (int i = 0; i < 4; ++i) {
        const long r0 = row0 + wm + i * 16 + grp;
#pragma unroll
        for (int j = 0; j < 4; ++j) {
            const long gc = col0 + wn + j * 8 + tig * 2;
            float x0 = acc[i][j][0] * scale, x1 = acc[i][j][1] * scale;
            float y0 = acc[i][j][2] * scale, y1 = acc[i][j][3] * scale;
            if (mask) {
                const bool m0 = mask[gc] != 0, m1 = mask[gc + 1] != 0;
                if (m0) { x0 = -FLT_MAX; y0 = -FLT_MAX; }
                if (m1) { x1 = -FLT_MAX; y1 = -FLT_MAX; }
            }
            *reinterpret_cast<float2*>(C + r0 * ldc + gc)       = make_float2(x0, x1);
            *reinterpret_cast<float2*>(C + (r0 + 8) * ldc + gc) = make_float2(y0, y1);
        }
    }
}

// ---------------------------------------------------------------------------
// Row softmax over LL (float4 I/O)
// ---------------------------------------------------------------------------
__global__ __launch_bounds__(256)
void softmax_kernel(float* __restrict__ S)
{
    __shared__ float4 buf[LL / 4];
    __shared__ float red[256];

    const int tid = threadIdx.x;
    float4* p = reinterpret_cast<float4*>(S + (long)blockIdx.x * LL);

    float m = -FLT_MAX;
#pragma unroll
    for (int i = tid; i < LL / 4; i += 256) {
        float4 v = p[i];
        buf[i] = v;
        m = fmaxf(m, fmaxf(fmaxf(v.x, v.y), fmaxf(v.z, v.w)));
    }
    red[tid] = m;
    __syncthreads();
    for (int s = 128; s > 0; s >>= 1) {
        if (tid < s) red[tid] = fmaxf(red[tid], red[tid + s]);
        __syncthreads();
    }
    m = red[0];
    __syncthreads();

    float sum = 0.0f;
#pragma unroll
    for (int i = tid; i < LL / 4; i += 256) {
        float4 v = buf[i];
        v.x = __expf(v.x - m); v.y = __expf(v.y - m);
        v.z = __expf(v.z - m); v.w = __expf(v.w - m);
        buf[i] = v;
        sum += v.x + v.y + v.z + v.w;
    }
    red[tid] = sum;
    __syncthreads();
    for (int s = 128; s > 0; s >>= 1) {
        if (tid < s) red[tid] += red[tid + s];
        __syncthreads();
    }
    const float inv = 1.0f / red[0];

#pragma unroll
    for (int i = tid; i < LL / 4; i += 256) {
        float4 v = buf[i];
        v.x *= inv; v.y *= inv; v.z *= inv; v.w *= inv;
        p[i] = v;
    }
}

// ---------------------------------------------------------------------------
// Launch. Inputs: H [B,L,DH] f32, G [B,T,DG] f32, mask [B,L] int32,
// Wk_w [P,DH] f32, Wq_w [P,DG] f32. Output Z [B,T,DH] f32.
// ---------------------------------------------------------------------------
extern "C" void kernel_launch(void* const* d_in, const int* in_sizes, int n_in,
                              void* d_out, int out_size)
{
    const float* H    = (const float*)d_in[0];
    const float* G    = (const float*)d_in[1];
    const int*   mask = (const int*)d_in[2];
    const float* Wk   = (const float*)d_in[3];
    const float* Wq   = (const float*)d_in[4];
    float*       Z    = (float*)d_out;

    float *gK, *gQ, *gS;
    cudaGetSymbolAddress((void**)&gK, g_K);
    cudaGetSymbolAddress((void**)&gQ, g_Q);
    cudaGetSymbolAddress((void**)&gS, g_S);

    cudaFuncSetAttribute(fp16x3_gemm<true>,
                         cudaFuncAttributeMaxDynamicSharedMemorySize, SMEM_GEMM);
    cudaFuncSetAttribute(fp16x3_gemm<false>,
                         cudaFuncAttributeMaxDynamicSharedMemorySize, SMEM_GEMM);

    // 1) K = H * Wk^T : [B*L, DH] x [P, DH]^T -> [B*L, P]
    fp16x3_gemm<true><<<dim3(PPQ / 128, (BB * LL) / 128, 1), 256, SMEM_GEMM>>>(
        H, Wk, gK, DHQ, DHQ, DHQ, PPQ, 0, 0, 0, 1.0f, nullptr, 0);

    // 2) Q = G * Wq^T : [B*T, DG] x [P, DG]^T -> [B*T, P]
    fp16x3_gemm<true><<<dim3(PPQ / 128, (BB * TTQ) / 128, 1), 256, SMEM_GEMM>>>(
        G, Wq, gQ, DGQ, DGQ, DGQ, PPQ, 0, 0, 0, 1.0f, nullptr, 0);

    // 3) S = scale * Q * K^T (masked) : per batch [T, P] x [L, P]^T -> [T, L]
    fp16x3_gemm<true><<<dim3(LL / 128, TTQ / 128, BB), 256, SMEM_GEMM>>>(
        gQ, gK, gS, PPQ, PPQ, PPQ, LL,
        (long)TTQ * PPQ, (long)LL * PPQ, (long)TTQ * LL,
        0.0625f, mask, (long)LL);

    // 4) softmax over L
    softmax_kernel<<<BB * TTQ, 256>>>(gS);

    // 5) Z = alpha * H : per batch [T, L] x [L, DH] (NN) -> [T, DH]
    fp16x3_gemm<false><<<dim3(DHQ / 128, TTQ / 128, BB), 256, SMEM_GEMM>>>(
        gS, H, Z, LL, LL, DHQ, DHQ,
        (long)TTQ * LL, (long)LL * DHQ, (long)TTQ * DHQ,
        1.0f, nullptr, 0);
}

// round 8
// speedup vs baseline: 1.9020x; 1.1692x over previous
#include <cuda_runtime.h>
#include <cuda_fp16.h>
#include <cstdint>
#include <float.h>

// Problem constants
#define BB 4
#define LL 4096
#define DHQ 1024
#define TTQ 1024
#define DGQ 768
#define PPQ 256

// Scratch (__device__ globals; no cudaMalloc allowed)
__device__ float g_K[(size_t)BB * LL * PPQ];   // 16 MB
__device__ float g_Q[(size_t)BB * TTQ * PPQ];  //  4 MB
__device__ float g_S[(size_t)BB * TTQ * LL];   // 64 MB

// ---------------------------------------------------------------------------
// helpers
// ---------------------------------------------------------------------------
__device__ __forceinline__ void mma_fp16(float* d, const uint32_t* a, const uint32_t* b) {
    asm volatile(
        "mma.sync.aligned.m16n8k16.row.col.f32.f16.f16.f32 "
        "{%0,%1,%2,%3}, {%4,%5,%6,%7}, {%8,%9}, {%0,%1,%2,%3};"
        : "+f"(d[0]), "+f"(d[1]), "+f"(d[2]), "+f"(d[3])
        : "r"(a[0]), "r"(a[1]), "r"(a[2]), "r"(a[3]), "r"(b[0]), "r"(b[1]));
}

__device__ __forceinline__ uint32_t h2_u32(__half2 h) {
    return *reinterpret_cast<uint32_t*>(&h);
}

// Split float pair -> (hi half2, lo half2). fp16 products are exact in fp32.
__device__ __forceinline__ void split2(float x, float y, uint32_t& hi, uint32_t& lo) {
    __half2 h = __floats2half2_rn(x, y);
    float2 hb = __half22float2(h);
    __half2 l = __floats2half2_rn(x - hb.x, y - hb.y);
    hi = h2_u32(h);
    lo = h2_u32(l);
}

// ---------------------------------------------------------------------------
// fp16 split tensor-core GEMM: C[M,N] = scale * A[M,K] * op(B)
//   BT=true : B is [N,K] row-major (NT);  BT=false: B is [K,N] row-major (NN)
//   TERMS=3: aH*bH + aH*bL + aL*bH  (rel err ~2^-22 class)
//   TERMS=2: aH*bH + aH*bL          (A effectively fp16; err ~2^-12 RMS)
// Block tile 128x128, BK=32, 256 threads (8 warps, 64x32 warp tiles).
// SMEM stages hold PRE-SPLIT half data:
//   A_hi [128][40] halves @0, A_lo @5120
//   NT B: B_hi [128][40] @10240, B_lo @15360
//   NN B: B_hi [32][136] @10240, B_lo @14592
// Stage = 20480 halves = 40960 B; 2 stages.
// Optional per-column int32 mask (logits): nonzero -> -FLT_MAX.
// ---------------------------------------------------------------------------
#define STAGE_H 20480
#define SMEM_GEMM (2 * STAGE_H * 2)   // 81920 bytes

template <bool BT, int TERMS>
__global__ __launch_bounds__(256)
void fp16x3_gemm(const float* __restrict__ A, const float* __restrict__ B,
                 float* __restrict__ C,
                 int K, long lda, long ldb, long ldc,
                 long sA, long sB, long sC,
                 float scale, const int* __restrict__ mask, long maskStride)
{
    extern __shared__ __align__(16) uint16_t smh[];

    const int tid  = threadIdx.x;
    const int wid  = tid >> 5;
    const int lane = tid & 31;
    const int grp  = lane >> 2;       // 0..7
    const int tig  = lane & 3;        // 0..3
    const int wm   = (wid & 1) * 64;  // warp m offset
    const int wn   = (wid >> 1) * 32; // warp n offset

    const int bz = blockIdx.z;
    A += (long)bz * sA;
    B += (long)bz * sB;
    C += (long)bz * sC;
    if (mask) mask += (long)bz * maskStride;

    const long row0 = (long)blockIdx.y * 128;
    const long col0 = (long)blockIdx.x * 128;

    const int nIter = K >> 5;   // BK = 32

    float4 rA[4], rB[4];

    auto load_tile = [&](int it) {
        const float* pA = A + row0 * lda + (long)it * 32;
#pragma unroll
        for (int p = 0; p < 4; ++p) {
            const int f = p * 256 + tid;
            rA[p] = *reinterpret_cast<const float4*>(pA + (long)(f >> 3) * lda + (f & 7) * 4);
        }
        if (BT) {
            const float* pB = B + col0 * ldb + (long)it * 32;
#pragma unroll
            for (int p = 0; p < 4; ++p) {
                const int f = p * 256 + tid;
                rB[p] = *reinterpret_cast<const float4*>(pB + (long)(f >> 3) * ldb + (f & 7) * 4);
            }
        } else {
            const float* pB = B + (long)it * 32 * ldb + col0;
#pragma unroll
            for (int p = 0; p < 4; ++p) {
                const int f = p * 256 + tid;
                rB[p] = *reinterpret_cast<const float4*>(pB + (long)(f >> 5) * ldb + (f & 31) * 4);
            }
        }
    };

    auto store_tile = [&](uint16_t* st) {
#pragma unroll
        for (int p = 0; p < 4; ++p) {
            const int f = p * 256 + tid;
            {   // A: [m][40] halves, hi @0, lo @5120
                const int m = f >> 3, kc = (f & 7) * 4;
                float4 v = rA[p];
                uint32_t h0, l0, h1, l1;
                split2(v.x, v.y, h0, l0);
                split2(v.z, v.w, h1, l1);
                *reinterpret_cast<uint2*>(st + m * 40 + kc) = make_uint2(h0, h1);
                if (TERMS == 3)
                    *reinterpret_cast<uint2*>(st + 5120 + m * 40 + kc) = make_uint2(l0, l1);
            }
            if (BT) {   // B: [n][40] halves, hi @10240, lo @15360
                const int n = f >> 3, kc = (f & 7) * 4;
                float4 v = rB[p];
                uint32_t h0, l0, h1, l1;
                split2(v.x, v.y, h0, l0);
                split2(v.z, v.w, h1, l1);
                *reinterpret_cast<uint2*>(st + 10240 + n * 40 + kc) = make_uint2(h0, h1);
                *reinterpret_cast<uint2*>(st + 15360 + n * 40 + kc) = make_uint2(l0, l1);
            } else {    // B: [k][136] halves, hi @10240, lo @14592
                const int k = f >> 5, nc = (f & 31) * 4;
                float4 v = rB[p];
                uint32_t h0, l0, h1, l1;
                split2(v.x, v.y, h0, l0);
                split2(v.z, v.w, h1, l1);
                *reinterpret_cast<uint2*>(st + 10240 + k * 136 + nc) = make_uint2(h0, h1);
                *reinterpret_cast<uint2*>(st + 14592 + k * 136 + nc) = make_uint2(l0, l1);
            }
        }
    };

    float acc[4][4][4];
#pragma unroll
    for (int i = 0; i < 4; ++i)
#pragma unroll
        for (int j = 0; j < 4; ++j)
#pragma unroll
            for (int r = 0; r < 4; ++r) acc[i][j][r] = 0.0f;

    load_tile(0);
    store_tile(smh);
    __syncthreads();

    for (int it = 0; it < nIter; ++it) {
        const bool more = (it + 1 < nIter);
        if (more) load_tile(it + 1);

        const uint16_t* st = smh + (it & 1) * STAGE_H;
        const uint32_t* sw = reinterpret_cast<const uint32_t*>(st);

#pragma unroll
        for (int ks = 0; ks < 2; ++ks) {
            uint32_t aH[4][4], aL[4][4], bH[4][2], bL[4][2];
#pragma unroll
            for (int i = 0; i < 4; ++i) {
                const int r  = wm + i * 16 + grp;
                const int w0 = r * 20 + tig + 8 * ks;
                const int w1 = (r + 8) * 20 + tig + 8 * ks;
                aH[i][0] = sw[w0];     aH[i][1] = sw[w1];
                aH[i][2] = sw[w0 + 4]; aH[i][3] = sw[w1 + 4];
                if (TERMS == 3) {
                    aL[i][0] = sw[2560 + w0];     aL[i][1] = sw[2560 + w1];
                    aL[i][2] = sw[2560 + w0 + 4]; aL[i][3] = sw[2560 + w1 + 4];
                }
            }
#pragma unroll
            for (int j = 0; j < 4; ++j) {
                const int n = wn + j * 8 + grp;
                if (BT) {
                    const int w0 = 5120 + n * 20 + tig + 8 * ks;
                    bH[j][0] = sw[w0];        bH[j][1] = sw[w0 + 4];
                    bL[j][0] = sw[2560 + w0]; bL[j][1] = sw[2560 + w0 + 4];
                } else {
                    const int kb = 2 * tig + 16 * ks;
                    const uint16_t* bh = st + 10240;
                    const uint16_t* bl = st + 14592;
                    bH[j][0] = (uint32_t)bh[kb * 136 + n]       | ((uint32_t)bh[(kb + 1) * 136 + n] << 16);
                    bH[j][1] = (uint32_t)bh[(kb + 8) * 136 + n] | ((uint32_t)bh[(kb + 9) * 136 + n] << 16);
                    bL[j][0] = (uint32_t)bl[kb * 136 + n]       | ((uint32_t)bl[(kb + 1) * 136 + n] << 16);
                    bL[j][1] = (uint32_t)bl[(kb + 8) * 136 + n] | ((uint32_t)bl[(kb + 9) * 136 + n] << 16);
                }
            }
            // Issue terms as separate sweeps: dependent MMAs on the same
            // accumulator are 16 instructions apart.
#pragma unroll
            for (int i = 0; i < 4; ++i)
#pragma unroll
                for (int j = 0; j < 4; ++j)
                    mma_fp16(acc[i][j], aH[i], bH[j]);
#pragma unroll
            for (int i = 0; i < 4; ++i)
#pragma unroll
                for (int j = 0; j < 4; ++j)
                    mma_fp16(acc[i][j], aH[i], bL[j]);
            if (TERMS == 3) {
#pragma unroll
                for (int i = 0; i < 4; ++i)
#pragma unroll
                    for (int j = 0; j < 4; ++j)
                        mma_fp16(acc[i][j], aL[i], bH[j]);
            }
        }

        if (more) store_tile(smh + ((it + 1) & 1) * STAGE_H);
        __syncthreads();
    }

    // Epilogue: register -> gmem (float2 per row-pair), scale + mask
#pragma unroll
    for (int i = 0; i < 4; ++i) {
        const long r0 = row0 + wm + i * 16 + grp;
#pragma unroll
        for (int j = 0; j < 4; ++j) {
            const long gc = col0 + wn + j * 8 + tig * 2;
            float x0 = acc[i][j][0] * scale, x1 = acc[i][j][1] * scale;
            float y0 = acc[i][j][2] * scale, y1 = acc[i][j][3] * scale;
            if (mask) {
                const bool m0 = mask[gc] != 0, m1 = mask[gc + 1] != 0;
                if (m0) { x0 = -FLT_MAX; y0 = -FLT_MAX; }
                if (m1) { x1 = -FLT_MAX; y1 = -FLT_MAX; }
            }
            *reinterpret_cast<float2*>(C + r0 * ldc + gc)       = make_float2(x0, x1);
            *reinterpret_cast<float2*>(C + (r0 + 8) * ldc + gc) = make_float2(y0, y1);
        }
    }
}

// ---------------------------------------------------------------------------
// Row softmax over LL (float4 I/O)
// ---------------------------------------------------------------------------
__global__ __launch_bounds__(256)
void softmax_kernel(float* __restrict__ S)
{
    __shared__ float4 buf[LL / 4];
    __shared__ float red[256];

    const int tid = threadIdx.x;
    float4* p = reinterpret_cast<float4*>(S + (long)blockIdx.x * LL);

    float m = -FLT_MAX;
#pragma unroll
    for (int i = tid; i < LL / 4; i += 256) {
        float4 v = p[i];
        buf[i] = v;
        m = fmaxf(m, fmaxf(fmaxf(v.x, v.y), fmaxf(v.z, v.w)));
    }
    red[tid] = m;
    __syncthreads();
    for (int s = 128; s > 0; s >>= 1) {
        if (tid < s) red[tid] = fmaxf(red[tid], red[tid + s]);
        __syncthreads();
    }
    m = red[0];
    __syncthreads();

    float sum = 0.0f;
#pragma unroll
    for (int i = tid; i < LL / 4; i += 256) {
        float4 v = buf[i];
        v.x = __expf(v.x - m); v.y = __expf(v.y - m);
        v.z = __expf(v.z - m); v.w = __expf(v.w - m);
        buf[i] = v;
        sum += v.x + v.y + v.z + v.w;
    }
    red[tid] = sum;
    __syncthreads();
    for (int s = 128; s > 0; s >>= 1) {
        if (tid < s) red[tid] += red[tid + s];
        __syncthreads();
    }
    const float inv = 1.0f / red[0];

#pragma unroll
    for (int i = tid; i < LL / 4; i += 256) {
        float4 v = buf[i];
        v.x *= inv; v.y *= inv; v.z *= inv; v.w *= inv;
        p[i] = v;
    }
}

// ---------------------------------------------------------------------------
// Launch. Inputs: H [B,L,DH] f32, G [B,T,DG] f32, mask [B,L] int32,
// Wk_w [P,DH] f32, Wq_w [P,DG] f32. Output Z [B,T,DH] f32.
// ---------------------------------------------------------------------------
extern "C" void kernel_launch(void* const* d_in, const int* in_sizes, int n_in,
                              void* d_out, int out_size)
{
    const float* H    = (const float*)d_in[0];
    const float* G    = (const float*)d_in[1];
    const int*   mask = (const int*)d_in[2];
    const float* Wk   = (const float*)d_in[3];
    const float* Wq   = (const float*)d_in[4];
    float*       Z    = (float*)d_out;

    float *gK, *gQ, *gS;
    cudaGetSymbolAddress((void**)&gK, g_K);
    cudaGetSymbolAddress((void**)&gQ, g_Q);
    cudaGetSymbolAddress((void**)&gS, g_S);

    cudaFuncSetAttribute(fp16x3_gemm<true, 3>,
                         cudaFuncAttributeMaxDynamicSharedMemorySize, SMEM_GEMM);
    cudaFuncSetAttribute(fp16x3_gemm<false, 2>,
                         cudaFuncAttributeMaxDynamicSharedMemorySize, SMEM_GEMM);

    // 1) K = H * Wk^T : [B*L, DH] x [P, DH]^T -> [B*L, P]
    fp16x3_gemm<true, 3><<<dim3(PPQ / 128, (BB * LL) / 128, 1), 256, SMEM_GEMM>>>(
        H, Wk, gK, DHQ, DHQ, DHQ, PPQ, 0, 0, 0, 1.0f, nullptr, 0);

    // 2) Q = G * Wq^T : [B*T, DG] x [P, DG]^T -> [B*T, P]
    fp16x3_gemm<true, 3><<<dim3(PPQ / 128, (BB * TTQ) / 128, 1), 256, SMEM_GEMM>>>(
        G, Wq, gQ, DGQ, DGQ, DGQ, PPQ, 0, 0, 0, 1.0f, nullptr, 0);

    // 3) S = scale * Q * K^T (masked) : per batch [T, P] x [L, P]^T -> [T, L]
    fp16x3_gemm<true, 3><<<dim3(LL / 128, TTQ / 128, BB), 256, SMEM_GEMM>>>(
        gQ, gK, gS, PPQ, PPQ, PPQ, LL,
        (long)TTQ * PPQ, (long)LL * PPQ, (long)TTQ * LL,
        0.0625f, mask, (long)LL);

    // 4) softmax over L
    softmax_kernel<<<BB * TTQ, 256>>>(gS);

    // 5) Z = alpha * H : per batch [T, L] x [L, DH] (NN) -> [T, DH]
    //    2-term: alphaH * (H_hi + H_lo) — H exact to 22 bits, alpha fp16.
    fp16x3_gemm<false, 2><<<dim3(DHQ / 128, TTQ / 128, BB), 256, SMEM_GEMM>>>(
        gS, H, Z, LL, LL, DHQ, DHQ,
        (long)TTQ * LL, (long)LL * DHQ, (long)TTQ * DHQ,
        1.0f, nullptr, 0);
}